// round 1
// baseline (speedup 1.0000x reference)
#include <cuda_runtime.h>

// Shapes (fixed by the problem)
#define NHEADS 8
#define TQ 4
#define QH 16
#define QW 16
#define TK 4
#define KH 16
#define KW 16
#define DIM 64
#define NB 4

#define PS 65   // padded smem row stride (conflict-free for lane-varying rows)

__global__ __launch_bounds__(256, 8)
void relpos_kernel(const float* __restrict__ query,
                   const float* __restrict__ scores,
                   const float* __restrict__ Hemb,   // [31, 64]
                   const float* __restrict__ Wemb,   // [31, 64]
                   const float* __restrict__ Temb,   // [7, 64]
                   float* __restrict__ out)
{
    __shared__ float sQ[QW][PS];
    __shared__ float sH[KH][PS];
    __shared__ float sW[31][PS];
    __shared__ float sT[TK][PS];
    __shared__ float relH[QW][KH];
    __shared__ float relW[QW][KW];
    __shared__ float relT[QW][TK];

    const int bid = blockIdx.x;          // 0..2047 = ((b*8+N)*4 + t)*16 + h
    const int h   = bid & 15;
    const int t   = (bid >> 4) & 3;
    const int bn  = bid >> 6;            // b*8 + N, 0..31
    const int tid = threadIdx.x;

    // ---- Stage: 16 query vectors (contiguous 4 KB)
    const float* qbase = query + ((size_t)bn * 1024 + t * 256 + h * 16) * DIM;
    for (int i = tid; i < QW * DIM; i += 256) {
        int w = i >> 6, c = i & 63;
        sQ[w][c] = qbase[i];
    }
    // ---- Stage: H rows, reordered so sH[kh] = Hemb[h - kh + 15]
    for (int i = tid; i < KH * DIM; i += 256) {
        int kh = i >> 6, c = i & 63;
        sH[kh][c] = Hemb[(h + 15 - kh) * DIM + c];
    }
    // ---- Stage: full W table (all 31 rows are used across w,kw)
    for (int i = tid; i < 31 * DIM; i += 256) {
        int r = i >> 6, c = i & 63;
        sW[r][c] = Wemb[i];
    }
    // ---- Stage: T rows, sT[kt] = Temb[t - kt + 3]
    for (int i = tid; i < TK * DIM; i += 256) {
        int kt = i >> 6, c = i & 63;
        sT[kt][c] = Temb[(t + 3 - kt) * DIM + c];
    }
    __syncthreads();

    // ---- Phase 2: 16 queries x 36 dots = 576 dot products (64-dim each)
    for (int d = tid; d < QW * 36; d += 256) {
        int w  = d / 36;
        int jj = d - w * 36;
        const float* tab;
        if (jj < 16)      tab = sH[jj];                        // kh = jj
        else if (jj < 32) tab = sW[w - (jj - 16) + 15];        // kw = jj-16
        else              tab = sT[jj - 32];                   // kt = jj-32
        const float* qv = sQ[w];
        float acc = 0.f;
        #pragma unroll
        for (int c = 0; c < DIM; c++) acc += qv[c] * tab[c];
        if (jj < 16)      relH[w][jj]      = acc;
        else if (jj < 32) relW[w][jj - 16] = acc;
        else              relT[w][jj - 32] = acc;
    }
    __syncthreads();

    // ---- Phase 3: stream 16 contiguous output rows (64 KB in, 64 KB out)
    const size_t rowbase = ((size_t)bn * 1024 + t * 256 + h * 16) * 1024;
    const float4* sc4 = (const float4*)(scores + rowbase);
    float4*       ot4 = (float4*)(out + rowbase);

    #pragma unroll 4
    for (int v = tid; v < QW * 256; v += 256) {
        int w   = v >> 8;          // query row within block
        int p   = v & 255;         // float4 index within row
        int kt  = p >> 6;
        int kh  = (p >> 2) & 15;
        int kw4 = (p & 3) << 2;
        float4 s = sc4[v];
        float base = relH[w][kh] + relT[w][kt];
        const float* rw = &relW[w][kw4];
        s.x += base + rw[0];
        s.y += base + rw[1];
        s.z += base + rw[2];
        s.w += base + rw[3];
        ot4[v] = s;
    }
}

extern "C" void kernel_launch(void* const* d_in, const int* in_sizes, int n_in,
                              void* d_out, int out_size) {
    const float* query  = (const float*)d_in[0];
    const float* scores = (const float*)d_in[1];
    const float* Hemb   = (const float*)d_in[2];
    const float* Wemb   = (const float*)d_in[3];
    const float* Temb   = (const float*)d_in[4];
    float* out = (float*)d_out;
    relpos_kernel<<<2048, 256>>>(query, scores, Hemb, Wemb, Temb, out);
}